// round 9
// baseline (speedup 1.0000x reference)
#include <cuda_runtime.h>
#include <cuda_bf16.h>
#include <float.h>

// PlanPredCollisionLoss: B=128, A=1024, M=6, T=16
// inputs: [0] ego_plan [B,T,2] f32
//         [1] agent_fut_preds [B,A,M,T,2] f32
//         [2] agent_score_preds [B,A,M] f32
//         [3] ego_plan_mask [B,T] f32
// output: scalar f32 mean loss

#define BB 128
#define AA 1024
#define MM 6
#define TT 16
#define QQ 4              /* blocks per batch */
#define NW 8              /* warps per block (256 threads) */

#define AGENT_THRESH 0.5f
#define X_DIS_THRESH 1.5f
#define Y_DIS_THRESH 3.0f
#define DIS2_THRESH  9.0f   /* DIS_THRESH^2, avoids sqrt */

// cross-block scratch. Everything is either fully overwritten each launch or
// reset to 0 by its finisher -> graph-replay safe, no init kernel.
__device__ float    g_bx[BB][QQ][TT];
__device__ float    g_by[BB][QQ][TT];
__device__ float    g_partial[BB];
__device__ unsigned g_cnt_b[BB];
__device__ unsigned g_count;

__global__ void __launch_bounds__(256) ppcl_kernel(
    const float* __restrict__ ego,    // [B,T,2]
    const float* __restrict__ fut,    // [B,A,M,T,2]
    const float* __restrict__ sc,     // [B,A,M]
    const float* __restrict__ mask,   // [B,T]
    float* __restrict__ out)
{
    const int b    = blockIdx.x >> 2;
    const int q    = blockIdx.x & 3;
    const int tid  = threadIdx.x;
    const int warp = tid >> 5;
    const int lane = tid & 31;
    const int grp  = lane >> 3;       // 0..3 : which agent within an iter
    const int j    = lane & 7;        // timestep pair index: t = 2j, 2j+1

    __shared__ float s_rx[NW][TT];
    __shared__ float s_ry[NW][TT];

    // ego pair for this lane: (x(2j), y(2j), x(2j+1), y(2j+1))
    const float4 e = reinterpret_cast<const float4*>(ego + b * TT * 2)[j];

    // ---- per-lane argmax over M=6 modes; agent a = q*256 + warp*32 + lane ----
    const int a = q * 256 + warp * 32 + lane;
    const float2* s2 = reinterpret_cast<const float2*>(
        sc + ((size_t)b * AA + a) * MM);           // 24B stride, 8B aligned
    const float2 p0 = s2[0], p1 = s2[1], p2 = s2[2];
    float smax = p0.x; int bm = 0;
    if (p0.y > smax) { smax = p0.y; bm = 1; }
    if (p1.x > smax) { smax = p1.x; bm = 2; }
    if (p1.y > smax) { smax = p1.y; bm = 3; }
    if (p2.x > smax) { smax = p2.x; bm = 4; }
    if (p2.y > smax) { smax = p2.y; bm = 5; }
    const int packed = (((a * MM + bm) * (TT * 2)) << 1) |
                       ((smax < AGENT_THRESH) ? 1 : 0);

    // ---- warp-autonomous min over this warp's 32 agents (4 agents / iter) ----
    const float* fut_b = fut + (size_t)b * AA * MM * (TT * 2);

    float xm0 = FLT_MAX, ym0 = FLT_MAX;   // t = 2j
    float xm1 = FLT_MAX, ym1 = FLT_MAX;   // t = 2j+1
#pragma unroll
    for (int i = 0; i < 8; i++) {
        const int pk = __shfl_sync(0xFFFFFFFFu, packed, 4 * i + grp);
        const float4 p = *reinterpret_cast<const float4*>(
            fut_b + (pk >> 1) + 4 * j);
        const int low = pk & 1;
        {
            const float dx = e.x - p.x;
            const float dy = e.y - p.y;
            const float d2 = dx * dx + dy * dy;
            const float pen = (d2 > DIS2_THRESH || low) ? 100.0f : 0.0f;
            xm0 = fminf(xm0, fabsf(dx) + pen);
            ym0 = fminf(ym0, fabsf(dy) + pen);
        }
        {
            const float dx = e.z - p.z;
            const float dy = e.w - p.w;
            const float d2 = dx * dx + dy * dy;
            const float pen = (d2 > DIS2_THRESH || low) ? 100.0f : 0.0f;
            xm1 = fminf(xm1, fabsf(dx) + pen);
            ym1 = fminf(ym1, fabsf(dy) + pen);
        }
    }
    // reduce across the 4 agent-groups (lanes {j, j+8, j+16, j+24})
#pragma unroll
    for (int off = 8; off <= 16; off <<= 1) {
        xm0 = fminf(xm0, __shfl_xor_sync(0xFFFFFFFFu, xm0, off));
        ym0 = fminf(ym0, __shfl_xor_sync(0xFFFFFFFFu, ym0, off));
        xm1 = fminf(xm1, __shfl_xor_sync(0xFFFFFFFFu, xm1, off));
        ym1 = fminf(ym1, __shfl_xor_sync(0xFFFFFFFFu, ym1, off));
    }
    if (lane < 8) {
        s_rx[warp][2 * j]     = xm0;  s_ry[warp][2 * j]     = ym0;
        s_rx[warp][2 * j + 1] = xm1;  s_ry[warp][2 * j + 1] = ym1;
    }
    __syncthreads();

    // ---- tail: warp 0 only ----
    if (warp == 0) {
        const int t = lane & 15;
        // block-level min across 8 warps: lanes 0-15 -> x, lanes 16-31 -> y
        float mv;
        if (lane < 16) {
            mv = s_rx[0][t];
#pragma unroll
            for (int w = 1; w < NW; w++) mv = fminf(mv, s_rx[w][t]);
            g_bx[b][q][t] = mv;
        } else {
            mv = s_ry[0][t];
#pragma unroll
            for (int w = 1; w < NW; w++) mv = fminf(mv, s_ry[w][t]);
            g_by[b][q][t] = mv;
        }
        __threadfence();
        __syncwarp();

        unsigned cb = 0;
        if (lane == 0) cb = atomicAdd(&g_cnt_b[b], 1u) + 1u;
        cb = __shfl_sync(0xFFFFFFFFu, cb, 0);

        if (cb == QQ) {
            // per-batch finisher: combine the 4 block minima, apply loss+mask
            __threadfence();
            float m;
            if (lane < 16) {
                const volatile float* px = &g_bx[b][0][t];
                m = fminf(fminf(px[0], px[TT]), fminf(px[2 * TT], px[3 * TT]));
            } else {
                const volatile float* py = &g_by[b][0][t];
                m = fminf(fminf(py[0], py[TT]), fminf(py[2 * TT], py[3 * TT]));
            }
            const float thr = (lane < 16) ? X_DIS_THRESH : Y_DIS_THRESH;
            const float l_  = (m <= thr) ? (thr - m) : 0.0f;
            float v = l_ * mask[b * TT + t];
#pragma unroll
            for (int off = 16; off > 0; off >>= 1)
                v += __shfl_xor_sync(0xFFFFFFFFu, v, off);

            unsigned cg = 0;
            if (lane == 0) {
                g_partial[b] = v;
                g_cnt_b[b]   = 0;            // reset for next replay
                __threadfence();
                cg = atomicAdd(&g_count, 1u) + 1u;
            }
            cg = __shfl_sync(0xFFFFFFFFu, cg, 0);

            if (cg == BB) {
                // global finisher: fixed-order sum of 128 partials
                __threadfence();
                const volatile float* gp = g_partial;
                float s = gp[lane * 4] + gp[lane * 4 + 1]
                        + gp[lane * 4 + 2] + gp[lane * 4 + 3];
#pragma unroll
                for (int off = 16; off > 0; off >>= 1)
                    s += __shfl_xor_sync(0xFFFFFFFFu, s, off);
                if (lane == 0) {
                    out[0] = s * (1.0f / (float)(BB * TT * 2));  // LOSS_WEIGHT=1
                    g_count = 0;                                  // reset for replay
                    __threadfence();
                }
            }
        }
    }
}

extern "C" void kernel_launch(void* const* d_in, const int* in_sizes, int n_in,
                              void* d_out, int out_size) {
    const float* ego  = (const float*)d_in[0];
    const float* fut  = (const float*)d_in[1];
    const float* sc   = (const float*)d_in[2];
    const float* mask = (const float*)d_in[3];
    float* out = (float*)d_out;

    ppcl_kernel<<<BB * QQ, 256>>>(ego, fut, sc, mask, out);
}